// round 7
// baseline (speedup 1.0000x reference)
#include <cuda_runtime.h>

// Blur_80281528697499: depthwise UpFirDn2D(up=2, dn=2, 4x4) == 2x2 stencil
// with odd-odd filter taps. x:(8,256,128,128) f32 -> out same shape.
//
// R=4 double-batch strip + L2 prefetch:
//   one warp owns 8 rows, processed as two R=4 batches.
//   Entry: 5 LDG.128 (batch A rows) + 4 prefetch.global.L2 (batch B rows)
//   -> 9 DRAM requests in flight with only 5 live float4s (32-40 regs).
//   Batch B reuses row y0+4 from registers (reads/output = 1.125) and its
//   LDGs hit L2 thanks to the prefetch.
// Block = 8 warps = 64 rows; plane = 2 blocks; grid = 2048*2 = 4096.

#define NB 8
#define NC 256
#define NH 128
#define NW 128

__device__ __forceinline__ void pf_l2(const void* p) {
    asm volatile("prefetch.global.L2 [%0];" :: "l"(p));
}

__global__ void __launch_bounds__(256) blur2x2_pf_kernel(
    const float* __restrict__ x,
    const float* __restrict__ filt,
    float* __restrict__ out)
{
    const int pblk  = blockIdx.x & 1;          // 2 blocks per plane
    const int plane = blockIdx.x >> 1;         // b*C + c, 0..2047
    const int c     = plane & (NC - 1);

    const int warp  = threadIdx.x >> 5;
    const int lane  = threadIdx.x & 31;
    const int y0    = pblk * 64 + warp * 8;    // first of 8 output rows

    const float4* rowp = reinterpret_cast<const float4*>(
        x + (size_t)plane * (NH * NW)) + y0 * (NW / 4) + lane;

    // Batch A loads: rows y0..y0+4 (y0+4 <= 124, always in range).
    float4 r[5];
    #pragma unroll
    for (int i = 0; i < 5; i++)
        r[i] = rowp[i * (NW / 4)];

    // Batch B prefetches: rows y0+5..y0+8 (row y0+8 only if it exists).
    const bool lastB = (y0 + 8 >= NH);         // warp-uniform
    #pragma unroll
    for (int j = 0; j < 3; j++)
        pf_l2(rowp + (5 + j) * (NW / 4));
    if (!lastB)
        pf_l2(rowp + 8 * (NW / 4));

    // Per-channel filter taps (only odd-odd taps of the 4x4 contribute).
    const float* fp = filt + c * 16;
    const float wA = __ldg(fp + 5);    // f[1][1]
    const float wB = __ldg(fp + 7);    // f[1][3]
    const float wC = __ldg(fp + 13);   // f[3][1]
    const float wD = __ldg(fp + 15);   // f[3][3]

    float4* obase = reinterpret_cast<float4*>(out) +
                    (size_t)plane * (NH * NW / 4) + y0 * (NW / 4) + lane;

    // ---- Batch A: output rows y0..y0+3 ----
    {
        float n[5];
        #pragma unroll
        for (int i = 0; i < 5; i++) {
            n[i] = __shfl_down_sync(0xffffffffu, r[i].x, 1);
            if (lane == 31) n[i] = 0.0f;       // right boundary -> 0
        }
        #pragma unroll
        for (int i = 0; i < 4; i++) {
            const float4 a = r[i], b = r[i + 1];
            float4 o;
            o.x = wA * a.x + wB * a.y + wC * b.x + wD * b.y;
            o.y = wA * a.y + wB * a.z + wC * b.y + wD * b.z;
            o.z = wA * a.z + wB * a.w + wC * b.z + wD * b.w;
            o.w = wA * a.w + wB * n[i] + wC * b.w + wD * n[i + 1];
            obase[i * (NW / 4)] = o;
        }
    }

    // ---- Batch B loads: reuse row y0+4, load y0+5..y0+8 (L2 hits) ----
    r[0] = r[4];
    #pragma unroll
    for (int j = 1; j < 4; j++)
        r[j] = rowp[(4 + j) * (NW / 4)];
    if (!lastB)
        r[4] = rowp[8 * (NW / 4)];
    else
        r[4] = make_float4(0.0f, 0.0f, 0.0f, 0.0f);  // bottom boundary

    // ---- Batch B: output rows y0+4..y0+7 ----
    {
        float n[5];
        #pragma unroll
        for (int i = 0; i < 5; i++) {
            n[i] = __shfl_down_sync(0xffffffffu, r[i].x, 1);
            if (lane == 31) n[i] = 0.0f;
        }
        #pragma unroll
        for (int i = 0; i < 4; i++) {
            const float4 a = r[i], b = r[i + 1];
            float4 o;
            o.x = wA * a.x + wB * a.y + wC * b.x + wD * b.y;
            o.y = wA * a.y + wB * a.z + wC * b.y + wD * b.z;
            o.z = wA * a.z + wB * a.w + wC * b.z + wD * b.w;
            o.w = wA * a.w + wB * n[i] + wC * b.w + wD * n[i + 1];
            obase[(4 + i) * (NW / 4)] = o;
        }
    }
}

extern "C" void kernel_launch(void* const* d_in, const int* in_sizes, int n_in,
                              void* d_out, int out_size)
{
    const float* x    = (const float*)d_in[0];   // (8,256,128,128) f32
    const float* filt = (const float*)d_in[1];   // (256,1,4,4) f32
    float* out = (float*)d_out;                  // (8,256,128,128) f32

    const int planes = NB * NC;                  // 2048
    const int blocks = planes * 2;               // 4096
    blur2x2_pf_kernel<<<blocks, 256>>>(x, filt, out);
}

// round 8
// speedup vs baseline: 1.0086x; 1.0086x over previous
#include <cuda_runtime.h>
#include <cstdint>

// Blur_80281528697499: depthwise UpFirDn2D(up=2, dn=2, 4x4) == 2x2 stencil
// with odd-odd filter taps. x:(8,256,128,128) f32 -> out same shape.
//
// cp.async staging version: one block = half a plane (64 output rows).
// Stage 65 input rows (64 + 1 halo; bottom halo zero-filled via cp.async
// zfill) into 33 KB SMEM with ~8 LDGSTS.16 per thread -> deep DRAM-level
// MLP with zero register cost. One __syncthreads, then each of 8 warps
// computes 8 rows from SMEM (conflict-free LDS.128, row reuse a<-b).
// Multiple blocks per SM overlap load and compute phases.

#define NB 8
#define NC 256
#define NH 128
#define NW 128
#define TILE_ROWS 65                    // 64 rows + 1 halo row
#define TILE_CHUNKS (TILE_ROWS * 32)    // float4 chunks = 2080

__device__ __forceinline__ uint32_t smem_u32(const void* p) {
    return (uint32_t)__cvta_generic_to_shared(p);
}

__global__ void __launch_bounds__(256) blur2x2_cpasync_kernel(
    const float* __restrict__ x,
    const float* __restrict__ filt,
    float* __restrict__ out)
{
    __shared__ float4 tile[TILE_CHUNKS];           // 33280 B

    const int pblk  = blockIdx.x & 1;              // 2 blocks per plane
    const int plane = blockIdx.x >> 1;             // b*C + c, 0..2047
    const int c     = plane & (NC - 1);
    const int tid   = threadIdx.x;
    const int y0    = pblk * 64;                   // first output row

    // ---- Stage 65 rows via cp.async (zfill for the nonexistent row 128) ----
    const float4* src = reinterpret_cast<const float4*>(
        x + (size_t)plane * (NH * NW)) + y0 * (NW / 4);
    // top block: all 65 rows valid; bottom block: only first 64 rows valid.
    const int n_valid = (pblk == 0) ? TILE_CHUNKS : 64 * 32;

    for (int i = tid; i < TILE_CHUNKS; i += 256) {
        const int  in_range  = (i < n_valid);
        const int  src_size  = in_range ? 16 : 0;          // 0 -> zero-fill
        const int  src_idx   = in_range ? i : 0;           // keep addr valid
        const uint32_t saddr = smem_u32(tile + i);
        asm volatile("cp.async.cg.shared.global [%0], [%1], 16, %2;"
                     :: "r"(saddr), "l"(src + src_idx), "r"(src_size));
    }
    asm volatile("cp.async.commit_group;");

    // Per-channel filter taps (only odd-odd taps of the 4x4 contribute),
    // loaded while the bulk copy is in flight.
    const float* fp = filt + c * 16;
    const float wA = __ldg(fp + 5);    // f[1][1]
    const float wB = __ldg(fp + 7);    // f[1][3]
    const float wC = __ldg(fp + 13);   // f[3][1]
    const float wD = __ldg(fp + 15);   // f[3][3]

    asm volatile("cp.async.wait_group 0;");
    __syncthreads();

    // ---- Compute: warp w handles local rows w*8 .. w*8+7 ----
    const int warp = tid >> 5;
    const int lane = tid & 31;
    const int lr0  = warp * 8;

    float4* obase = reinterpret_cast<float4*>(out) +
                    (size_t)plane * (NH * NW / 4) +
                    (y0 + lr0) * (NW / 4) + lane;

    float4 a  = tile[lr0 * 32 + lane];
    float  an = __shfl_down_sync(0xffffffffu, a.x, 1);
    if (lane == 31) an = 0.0f;                     // right boundary -> 0

    #pragma unroll
    for (int i = 0; i < 8; i++) {
        const float4 b = tile[(lr0 + i + 1) * 32 + lane];
        float bn = __shfl_down_sync(0xffffffffu, b.x, 1);
        if (lane == 31) bn = 0.0f;

        float4 o;
        o.x = wA * a.x + wB * a.y + wC * b.x + wD * b.y;
        o.y = wA * a.y + wB * a.z + wC * b.y + wD * b.z;
        o.z = wA * a.z + wB * a.w + wC * b.z + wD * b.w;
        o.w = wA * a.w + wB * an  + wC * b.w + wD * bn;
        obase[i * (NW / 4)] = o;

        a  = b;
        an = bn;
    }
}

extern "C" void kernel_launch(void* const* d_in, const int* in_sizes, int n_in,
                              void* d_out, int out_size)
{
    const float* x    = (const float*)d_in[0];   // (8,256,128,128) f32
    const float* filt = (const float*)d_in[1];   // (256,1,4,4) f32
    float* out = (float*)d_out;                  // (8,256,128,128) f32

    const int planes = NB * NC;                  // 2048
    const int blocks = planes * 2;               // 4096
    blur2x2_cpasync_kernel<<<blocks, 256>>>(x, filt, out);
}

// round 9
// speedup vs baseline: 1.0353x; 1.0265x over previous
#include <cuda_runtime.h>

// Blur_80281528697499: depthwise UpFirDn2D(up=2, dn=2, 4x4) == 2x2 stencil
// with odd-odd filter taps. x:(8,256,128,128) f32 -> out same shape.
//
// Best-measured structure (R=4 row-strip, 32 regs, MLP=5) with finer CTA
// granularity: 128-thread blocks (4 warps = 16 rows), grid = 2048*8 = 16384.
// Halves the per-CTA front-batched LDG count (cross-CTA L1tex queue
// contention / CTA spread) and smooths the wave tail vs 256-thr blocks.
// Per-warp: load 5 independent rows (LDG.128), compute 4 output rows with
// register reuse; x+4 neighbor via __shfl_down.

#define NB 8
#define NC 256
#define NH 128
#define NW 128
#define R  4   // output rows per warp

__global__ void __launch_bounds__(128) blur2x2_strip_kernel(
    const float* __restrict__ x,
    const float* __restrict__ filt,
    float* __restrict__ out)
{
    const int pblk  = blockIdx.x & 7;          // 8 blocks per plane
    const int plane = blockIdx.x >> 3;         // b*C + c, 0..2047
    const int c     = plane & (NC - 1);

    const int warp  = threadIdx.x >> 5;
    const int lane  = threadIdx.x & 31;
    const int y0    = pblk * 16 + warp * R;    // first output row of strip

    const float4* base = reinterpret_cast<const float4*>(
        x + (size_t)plane * (NH * NW));

    // Front-load R+1 = 5 rows (independent -> 5 LDG.128 in flight).
    float4 r[R + 1];
    const bool last_strip = (y0 + R >= NH);    // warp-uniform
    #pragma unroll
    for (int i = 0; i < R; i++)
        r[i] = base[(y0 + i) * (NW / 4) + lane];
    if (!last_strip)
        r[R] = base[(y0 + R) * (NW / 4) + lane];
    else
        r[R] = make_float4(0.0f, 0.0f, 0.0f, 0.0f);

    // Per-channel filter taps (only odd-odd taps of the 4x4 contribute).
    const float* fp = filt + c * 16;
    const float wA = __ldg(fp + 5);    // f[1][1]
    const float wB = __ldg(fp + 7);    // f[1][3]
    const float wC = __ldg(fp + 13);   // f[3][1]
    const float wD = __ldg(fp + 15);   // f[3][3]

    // Next-lane .x for each row (right neighbor of the .w element).
    float n[R + 1];
    #pragma unroll
    for (int i = 0; i < R + 1; i++) {
        n[i] = __shfl_down_sync(0xffffffffu, r[i].x, 1);
        if (lane == 31) n[i] = 0.0f;           // right boundary -> 0
    }

    float4* obase = reinterpret_cast<float4*>(out) +
                    (size_t)plane * (NH * NW / 4) + lane;

    #pragma unroll
    for (int i = 0; i < R; i++) {
        const float4 a = r[i];
        const float4 b = r[i + 1];
        float4 o;
        o.x = wA * a.x + wB * a.y + wC * b.x + wD * b.y;
        o.y = wA * a.y + wB * a.z + wC * b.y + wD * b.z;
        o.z = wA * a.z + wB * a.w + wC * b.z + wD * b.w;
        o.w = wA * a.w + wB * n[i] + wC * b.w + wD * n[i + 1];
        obase[(y0 + i) * (NW / 4)] = o;
    }
}

extern "C" void kernel_launch(void* const* d_in, const int* in_sizes, int n_in,
                              void* d_out, int out_size)
{
    const float* x    = (const float*)d_in[0];   // (8,256,128,128) f32
    const float* filt = (const float*)d_in[1];   // (256,1,4,4) f32
    float* out = (float*)d_out;                  // (8,256,128,128) f32

    const int planes = NB * NC;                  // 2048
    const int blocks = planes * 8;               // 16384
    blur2x2_strip_kernel<<<blocks, 128>>>(x, filt, out);
}